// round 14
// baseline (speedup 1.0000x reference)
#include <cuda_runtime.h>
#include <cuda_fp16.h>
#include <math.h>
#include <stdint.h>

// ---------------------------------------------------------------------------
// SwinTransformerBlock R12: mma.sync fp16 datapath (tcgen05 unavailable on the
// harness's plain-sm_103 ptxas target). GEMMs retiled to block 128x256 /
// warp 64x64 to cut LDSM+issue pressure per FLOP.
// B=8, H=W=128, C=256, NH=8, hd=32, WS=8, SS=4.
// ---------------------------------------------------------------------------

typedef __half hf;

#define MTOK 131072
#define C_DIM 256

// fp16 weight planes [K,N] layout, concatenated
#define OFF_QW    0
#define OFF_KVW   65536
#define OFF_PROJW 196608
#define OFF_FC1W  262144
#define OFF_FC2W  524288
__device__ hf g_w[786432];

__device__ hf g_rw[MTOK * C_DIM];
__device__ hf g_aw[MTOK * C_DIM];
__device__ hf g_q [MTOK * C_DIM];
__device__ hf g_kv[MTOK * 2 * C_DIM];
__device__ hf g_ao[MTOK * C_DIM];
__device__ hf g_h1[MTOK * C_DIM];
__device__ hf g_hb[MTOK * 1024];
__device__ float g_x[MTOK * C_DIM];

__device__ __forceinline__ int map_row(int i) {
    int b_ = i >> 6, n = i & 63;
    int bb = b_ >> 8, wi = b_ & 255;
    int sh = ((wi >> 4) << 3) + (n >> 3);
    int sw = ((wi & 15) << 3) + (n & 7);
    int gh = (sh + 4) & 127;
    int gw = (sw + 4) & 127;
    return (bb << 14) + (gh << 7) + gw;
}

__device__ __forceinline__ uint32_t smem_u32(const void* p) {
    return (uint32_t)__cvta_generic_to_shared(p);
}
__device__ __forceinline__ void ldsm4(uint32_t* r, uint32_t addr) {
    asm volatile("ldmatrix.sync.aligned.m8n8.x4.shared.b16 {%0,%1,%2,%3}, [%4];"
                 : "=r"(r[0]), "=r"(r[1]), "=r"(r[2]), "=r"(r[3]) : "r"(addr));
}
__device__ __forceinline__ void ldsm4t(uint32_t* r, uint32_t addr) {
    asm volatile("ldmatrix.sync.aligned.m8n8.x4.trans.shared.b16 {%0,%1,%2,%3}, [%4];"
                 : "=r"(r[0]), "=r"(r[1]), "=r"(r[2]), "=r"(r[3]) : "r"(addr));
}
__device__ __forceinline__ void mma_f16(float* c, const uint32_t* a, const uint32_t* b) {
    asm volatile("mma.sync.aligned.m16n8k16.row.col.f32.f16.f16.f32 "
                 "{%0,%1,%2,%3}, {%4,%5,%6,%7}, {%8,%9}, {%0,%1,%2,%3};"
                 : "+f"(c[0]), "+f"(c[1]), "+f"(c[2]), "+f"(c[3])
                 : "r"(a[0]), "r"(a[1]), "r"(a[2]), "r"(a[3]), "r"(b[0]), "r"(b[1]));
}
__device__ __forceinline__ void cp16(void* dst, const void* src) {
    asm volatile("cp.async.cg.shared.global [%0], [%1], 16;"
                 :: "r"(smem_u32(dst)), "l"(src));
}
__device__ __forceinline__ void cp_commit() { asm volatile("cp.async.commit_group;"); }

// ---------------------------------------------------------------------------
__global__ void cvt_kernel(const float* __restrict__ s, hf* __restrict__ d, int n)
{
    for (int i = blockIdx.x * blockDim.x + threadIdx.x; i < n; i += gridDim.x * blockDim.x)
        d[i] = __float2half(s[i]);
}

// ---------------------------------------------------------------------------
// LayerNorm: one warp per token, 8 tokens per block, fp16 out.
// ---------------------------------------------------------------------------
template<bool GATHER, bool DUAL>
__global__ void __launch_bounds__(256)
ln_kernel(const float* __restrict__ x1, const float* __restrict__ x2,
          const float* __restrict__ gam, const float* __restrict__ bet,
          hf* __restrict__ o1, hf* __restrict__ o2)
{
    int lane = threadIdx.x & 31, wid = threadIdx.x >> 5;
    int i = (blockIdx.x << 3) + wid;
    size_t base = (size_t)(GATHER ? map_row(i) : i) * C_DIM + (lane << 3);

    float a[8], b[8];
    *(float4*)(a)     = *(const float4*)&x1[base];
    *(float4*)(a + 4) = *(const float4*)&x1[base + 4];
    if (DUAL) {
        *(float4*)(b)     = *(const float4*)&x2[base];
        *(float4*)(b + 4) = *(const float4*)&x2[base + 4];
    }
    float s0 = 0, s1 = 0, s2 = 0, s3 = 0;
    #pragma unroll
    for (int j = 0; j < 8; j++) {
        s0 += a[j]; s1 += a[j] * a[j];
        if (DUAL) { s2 += b[j]; s3 += b[j] * b[j]; }
    }
    #pragma unroll
    for (int off = 16; off; off >>= 1) {
        s0 += __shfl_xor_sync(0xffffffffu, s0, off);
        s1 += __shfl_xor_sync(0xffffffffu, s1, off);
        if (DUAL) {
            s2 += __shfl_xor_sync(0xffffffffu, s2, off);
            s3 += __shfl_xor_sync(0xffffffffu, s3, off);
        }
    }
    float m1 = s0 * (1.0f / 256.0f);
    float r1 = rsqrtf(s1 * (1.0f / 256.0f) - m1 * m1 + 1e-5f);

    float g[8], bt[8];
    *(float4*)(g)      = *(const float4*)&gam[lane << 3];
    *(float4*)(g + 4)  = *(const float4*)&gam[(lane << 3) + 4];
    *(float4*)(bt)     = *(const float4*)&bet[lane << 3];
    *(float4*)(bt + 4) = *(const float4*)&bet[(lane << 3) + 4];

    size_t dst = (size_t)i * C_DIM + (lane << 3);
    hf t[8];
    #pragma unroll
    for (int j = 0; j < 8; j++) t[j] = __float2half((a[j] - m1) * r1 * g[j] + bt[j]);
    *(float4*)&o1[dst] = *(float4*)t;
    if (DUAL) {
        float m2 = s2 * (1.0f / 256.0f);
        float r2 = rsqrtf(s3 * (1.0f / 256.0f) - m2 * m2 + 1e-5f);
        #pragma unroll
        for (int j = 0; j < 8; j++) t[j] = __float2half((b[j] - m2) * r2 * g[j] + bt[j]);
        *(float4*)&o2[dst] = *(float4*)t;
    }
}

// ---------------------------------------------------------------------------
// fp16 tensor-core GEMM: C[M,N] = A[M,K] @ B[K,N] + bias.
// Block tile 128x256, warp tile 64x64 (8 warps, 2Mx4N). K-chunk 32, 2-stage
// cp.async. Dynamic SMEM 54.3KB.
// MODE 0: bias -> fp16 | 1: bias+GELU -> fp16
// MODE 2: bias+scatter(map_row)+aux -> fp32 | 3: bias+aux -> fp32
// ---------------------------------------------------------------------------
#define AS_N (128 * 40)            // one stage of A in hf
#define BS_N (32 * 264)            // one stage of B in hf
#define AS_IDX(st,r,c) (((st) * 128 + (r)) * 40 + (c))
#define BS_IDX(st,r,c) (((st) * 32 + (r)) * 264 + (c))
#define SMEM_GEMM ((2 * AS_N + 2 * BS_N) * 2)   // 54272 B

template<int MODE>
__global__ void __launch_bounds__(256, 1)
mma_gemm(const hf* __restrict__ Ah, const hf* __restrict__ Bh,
         const float* __restrict__ bias, const float* __restrict__ aux,
         hf* __restrict__ Chf, float* __restrict__ Cf,
         int M, int N, int K)
{
    extern __shared__ __align__(16) hf smg[];
    hf* As = smg;                   // [2][128][40]
    hf* Bs = smg + 2 * AS_N;        // [2][32][264]

    int tid = threadIdx.x;
    int lane = tid & 31, wid = tid >> 5;
    int wm = wid & 1, wn = wid >> 1;           // 2 M-warps x 4 N-warps
    int rowBase = blockIdx.y << 7, colBase = blockIdx.x << 8;

    float acc[4][8][4];
    #pragma unroll
    for (int i = 0; i < 4; i++)
        #pragma unroll
        for (int j = 0; j < 8; j++)
            #pragma unroll
            for (int p = 0; p < 4; p++) acc[i][j][p] = 0.0f;

    int nK = K >> 5;

    auto stage_load = [&](int st, int k0) {
        // A: 128x32 hf = 512 16B chunks, 2/thread
        #pragma unroll
        for (int l = 0; l < 2; l++) {
            int id = tid + (l << 8);
            int r = id >> 2, c8 = (id & 3) << 3;
            cp16(&As[AS_IDX(st, r, c8)], Ah + (size_t)(rowBase + r) * K + k0 + c8);
        }
        // B: 32x256 hf = 1024 16B chunks, 4/thread
        #pragma unroll
        for (int l = 0; l < 4; l++) {
            int id = tid + (l << 8);
            int r = id >> 5, c8 = (id & 31) << 3;
            cp16(&Bs[BS_IDX(st, r, c8)], Bh + (size_t)(k0 + r) * N + colBase + c8);
        }
    };

    stage_load(0, 0);
    cp_commit();

    for (int kt = 0; kt < nK; kt++) {
        if (kt + 1 < nK) {
            stage_load((kt + 1) & 1, (kt + 1) << 5);
            cp_commit();
            asm volatile("cp.async.wait_group 1;");
        } else {
            asm volatile("cp.async.wait_group 0;");
        }
        __syncthreads();

        int s = kt & 1;
        #pragma unroll
        for (int kk = 0; kk < 32; kk += 16) {
            uint32_t af[4][4];
            #pragma unroll
            for (int im = 0; im < 4; im++)
                ldsm4(af[im], smem_u32(&As[AS_IDX(s, wm * 64 + im * 16 + (lane & 15),
                                                  kk + ((lane >> 4) << 3))]));
            uint32_t bfr[4][4];
            #pragma unroll
            for (int jg = 0; jg < 4; jg++)
                ldsm4t(bfr[jg], smem_u32(&Bs[BS_IDX(s, kk + (lane & 15),
                                                    wn * 64 + jg * 16 + ((lane >> 4) << 3))]));
            #pragma unroll
            for (int im = 0; im < 4; im++)
                #pragma unroll
                for (int jn = 0; jn < 8; jn++)
                    mma_f16(acc[im][jn], af[im], &bfr[jn >> 1][(jn & 1) << 1]);
        }
        __syncthreads();
    }

    // epilogue
    int g = lane >> 2, t2 = (lane & 3) << 1;
    #pragma unroll
    for (int im = 0; im < 4; im++) {
        #pragma unroll
        for (int half_ = 0; half_ < 2; half_++) {
            int row = rowBase + wm * 64 + im * 16 + g + half_ * 8;
            size_t drow = (MODE == 2) ? (size_t)map_row(row) : (size_t)row;
            #pragma unroll
            for (int jn = 0; jn < 8; jn++) {
                int col = colBase + wn * 64 + jn * 8 + t2;
                float v0 = acc[im][jn][half_ * 2 + 0] + bias[col];
                float v1 = acc[im][jn][half_ * 2 + 1] + bias[col + 1];
                if (MODE == 1) {
                    v0 = 0.5f * v0 * (1.0f + erff(v0 * 0.70710678118654752f));
                    v1 = 0.5f * v1 * (1.0f + erff(v1 * 0.70710678118654752f));
                }
                if (MODE <= 1) {
                    __half2 t;
                    t.x = __float2half(v0);
                    t.y = __float2half(v1);
                    *(__half2*)(Chf + drow * (size_t)N + col) = t;
                } else {
                    const float* ax = aux + drow * (size_t)N + col;
                    *(float2*)(Cf + drow * (size_t)N + col) =
                        make_float2(v0 + ax[0], v1 + ax[1]);
                }
            }
        }
    }
}

// ---------------------------------------------------------------------------
// fp16 mma.sync attention: one block per (window, head), 256 threads.
// ---------------------------------------------------------------------------
__global__ void __launch_bounds__(256)
attn_kernel(const hf* __restrict__ Q, const hf* __restrict__ KV,
            const float* __restrict__ mask, const float* __restrict__ rel,
            hf* __restrict__ O)
{
    __shared__ __align__(16) hf qs[64 * 40];
    __shared__ __align__(16) hf ks[64 * 40];
    __shared__ __align__(16) hf vs[64 * 40];
    __shared__ __align__(16) float sc[64 * 68];
    __shared__ __align__(16) hf ps[64 * 72];

    int b_ = blockIdx.x, h = blockIdx.y, wi = b_ & 255;
    int tid = threadIdx.x, lane = tid & 31, wid = tid >> 5;
    int wm = wid & 3, wn = wid >> 2;

    #pragma unroll
    for (int l = 0; l < 3; l++) {
        int id = tid + (l << 8);
        int tsr = id >> 8;
        int rem = id & 255;
        int r = rem >> 2, c8 = (rem & 3) << 3;
        const hf* gsrc;
        hf* dst;
        if (tsr == 0) { gsrc = Q  + (size_t)(b_ * 64 + r) * 256 + h * 32 + c8;       dst = qs + r * 40 + c8; }
        else if (tsr == 1) { gsrc = KV + (size_t)(b_ * 64 + r) * 512 + h * 32 + c8;  dst = ks + r * 40 + c8; }
        else { gsrc = KV + (size_t)(b_ * 64 + r) * 512 + 256 + h * 32 + c8;          dst = vs + r * 40 + c8; }
        *(float4*)dst = *(const float4*)gsrc;
    }
    __syncthreads();

    float accS[4][4];
    #pragma unroll
    for (int j = 0; j < 4; j++)
        #pragma unroll
        for (int p = 0; p < 4; p++) accS[j][p] = 0.0f;

    #pragma unroll
    for (int kk = 0; kk < 32; kk += 16) {
        uint32_t ah[4];
        ldsm4(ah, smem_u32(qs + (wm * 16 + (lane & 15)) * 40 + kk + ((lane >> 4) << 3)));
        #pragma unroll
        for (int jg = 0; jg < 2; jg++) {
            int nrow = wn * 32 + jg * 16 + ((lane >> 4) << 3) + (lane & 7);
            int kcol = kk + (((lane >> 3) & 1) << 3);
            uint32_t bh[4];
            ldsm4(bh, smem_u32(ks + nrow * 40 + kcol));
            #pragma unroll
            for (int t = 0; t < 2; t++)
                mma_f16(accS[jg * 2 + t], ah, bh + t * 2);
        }
    }

    const float scale = 0.17677669529663687f;
    int g = lane >> 2, t2 = (lane & 3) << 1;
    #pragma unroll
    for (int jn = 0; jn < 4; jn++) {
        int col = wn * 32 + jn * 8 + t2;
        #pragma unroll
        for (int half_ = 0; half_ < 2; half_++) {
            int n = wm * 16 + g + half_ * 8;
            #pragma unroll
            for (int u = 0; u < 2; u++) {
                int m = col + u;
                int dr = (n >> 3) - (m >> 3) + 7;
                int dc = (n & 7) - (m & 7) + 7;
                sc[n * 68 + m] = accS[jn][half_ * 2 + u] * scale
                                 + rel[(dr * 15 + dc) * 8 + h]
                                 + mask[(size_t)wi * 4096 + n * 64 + m];
            }
        }
    }
    __syncthreads();

    {
        int row = tid >> 2, p = tid & 3;
        float e[16];
        float mx = -1e30f;
        #pragma unroll
        for (int j = 0; j < 16; j++) {
            e[j] = sc[row * 68 + p * 16 + j];
            mx = fmaxf(mx, e[j]);
        }
        mx = fmaxf(mx, __shfl_xor_sync(0xffffffffu, mx, 1));
        mx = fmaxf(mx, __shfl_xor_sync(0xffffffffu, mx, 2));
        float s = 0.0f;
        #pragma unroll
        for (int j = 0; j < 16; j++) { e[j] = __expf(e[j] - mx); s += e[j]; }
        s += __shfl_xor_sync(0xffffffffu, s, 1);
        s += __shfl_xor_sync(0xffffffffu, s, 2);
        float inv = 1.0f / s;
        hf t[16];
        #pragma unroll
        for (int j = 0; j < 16; j++) t[j] = __float2half(e[j] * inv);
        #pragma unroll
        for (int j = 0; j < 16; j += 8)
            *(float4*)&ps[row * 72 + p * 16 + j] = *(float4*)&t[j];
    }
    __syncthreads();

    float accO[2][4];
    #pragma unroll
    for (int t = 0; t < 2; t++)
        #pragma unroll
        for (int p = 0; p < 4; p++) accO[t][p] = 0.0f;

    #pragma unroll
    for (int kk = 0; kk < 64; kk += 16) {
        uint32_t ah[4];
        ldsm4(ah, smem_u32(ps + (wm * 16 + (lane & 15)) * 72 + kk + ((lane >> 4) << 3)));
        uint32_t bh[4];
        ldsm4t(bh, smem_u32(vs + (kk + (lane & 15)) * 40 + wn * 16 + ((lane >> 4) << 3)));
        #pragma unroll
        for (int t = 0; t < 2; t++)
            mma_f16(accO[t], ah, bh + t * 2);
    }

    #pragma unroll
    for (int t = 0; t < 2; t++) {
        int col = h * 32 + wn * 16 + t * 8 + t2;
        #pragma unroll
        for (int half_ = 0; half_ < 2; half_++) {
            size_t row = (size_t)b_ * 64 + wm * 16 + g + half_ * 8;
            __half2 o;
            o.x = __float2half(accO[t][half_ * 2 + 0]);
            o.y = __float2half(accO[t][half_ * 2 + 1]);
            *(__half2*)(O + row * 256 + col) = o;
        }
    }
}

// ---------------------------------------------------------------------------
extern "C" void kernel_launch(void* const* d_in, const int* in_sizes, int n_in,
                              void* d_out, int out_size)
{
    const float* ref    = (const float*)d_in[0];
    const float* adj    = (const float*)d_in[1];
    const float* mask   = (const float*)d_in[2];
    const float* n1g    = (const float*)d_in[5];
    const float* n1b    = (const float*)d_in[6];
    const float* q_w    = (const float*)d_in[7];
    const float* q_b    = (const float*)d_in[8];
    const float* kv_w   = (const float*)d_in[9];
    const float* kv_b   = (const float*)d_in[10];
    const float* rel    = (const float*)d_in[11];
    const float* proj_w = (const float*)d_in[12];
    const float* proj_b = (const float*)d_in[13];
    const float* n2g    = (const float*)d_in[14];
    const float* n2b    = (const float*)d_in[15];
    const float* fc1_w  = (const float*)d_in[16];
    const float* fc1_b  = (const float*)d_in[17];
    const float* fc2_w  = (const float*)d_in[18];
    const float* fc2_b  = (const float*)d_in[19];
    float* out = (float*)d_out;

    hf *w, *rw, *aw, *q, *kv, *ao, *h1, *hb;
    float* x;
    cudaGetSymbolAddress((void**)&w,  g_w);
    cudaGetSymbolAddress((void**)&rw, g_rw);
    cudaGetSymbolAddress((void**)&aw, g_aw);
    cudaGetSymbolAddress((void**)&q,  g_q);
    cudaGetSymbolAddress((void**)&kv, g_kv);
    cudaGetSymbolAddress((void**)&ao, g_ao);
    cudaGetSymbolAddress((void**)&h1, g_h1);
    cudaGetSymbolAddress((void**)&hb, g_hb);
    cudaGetSymbolAddress((void**)&x,  g_x);

    cudaFuncSetAttribute(mma_gemm<0>, cudaFuncAttributeMaxDynamicSharedMemorySize, SMEM_GEMM);
    cudaFuncSetAttribute(mma_gemm<1>, cudaFuncAttributeMaxDynamicSharedMemorySize, SMEM_GEMM);
    cudaFuncSetAttribute(mma_gemm<2>, cudaFuncAttributeMaxDynamicSharedMemorySize, SMEM_GEMM);
    cudaFuncSetAttribute(mma_gemm<3>, cudaFuncAttributeMaxDynamicSharedMemorySize, SMEM_GEMM);

    const int M = MTOK;
    const dim3 blk256(256);

    // 0. weights -> fp16 ([K,N] layout preserved)
    cvt_kernel<<<64, 256>>>(q_w,    w + OFF_QW,    65536);
    cvt_kernel<<<128, 256>>>(kv_w,  w + OFF_KVW,   131072);
    cvt_kernel<<<64, 256>>>(proj_w, w + OFF_PROJW, 65536);
    cvt_kernel<<<256, 256>>>(fc1_w, w + OFF_FC1W,  262144);
    cvt_kernel<<<256, 256>>>(fc2_w, w + OFF_FC2W,  262144);

    // 1. LN1 + shift + window partition
    ln_kernel<true, true><<<M / 8, blk256>>>(ref, adj, n1g, n1b, rw, aw);

    // 2. Q and KV projections (N-tile = 256)
    mma_gemm<0><<<dim3(1, M / 128), blk256, SMEM_GEMM>>>(rw, w + OFF_QW,  q_b,  nullptr, q,  nullptr, M, 256, 256);
    mma_gemm<0><<<dim3(2, M / 128), blk256, SMEM_GEMM>>>(aw, w + OFF_KVW, kv_b, nullptr, kv, nullptr, M, 512, 256);

    // 3. windowed attention
    attn_kernel<<<dim3(2048, 8), blk256>>>(q, kv, mask, rel, ao);

    // 4. proj + window reverse + unshift + shortcut -> fp32 x
    mma_gemm<2><<<dim3(1, M / 128), blk256, SMEM_GEMM>>>(ao, w + OFF_PROJW, proj_b, ref, nullptr, x, M, 256, 256);

    // 5. MLP
    ln_kernel<false, false><<<M / 8, blk256>>>(x, nullptr, n2g, n2b, h1, nullptr);
    mma_gemm<1><<<dim3(4, M / 128), blk256, SMEM_GEMM>>>(h1, w + OFF_FC1W, fc1_b, nullptr, hb, nullptr, M, 1024, 256);
    mma_gemm<3><<<dim3(1, M / 128), blk256, SMEM_GEMM>>>(hb, w + OFF_FC2W, fc2_b, x, nullptr, out, M, 256, 1024);
}

// round 16
// speedup vs baseline: 1.1423x; 1.1423x over previous
#include <cuda_runtime.h>
#include <cuda_fp16.h>
#include <math.h>
#include <stdint.h>

// ---------------------------------------------------------------------------
// SwinTransformerBlock R15: R10 structure (proven 1231us) + K-chunk 64 GEMM
// (half the barriers) + single merged weight-convert kernel.
// B=8, H=W=128, C=256, NH=8, hd=32, WS=8, SS=4.
// ---------------------------------------------------------------------------

typedef __half hf;

#define MTOK 131072
#define C_DIM 256

#define OFF_QW    0
#define OFF_KVW   65536
#define OFF_PROJW 196608
#define OFF_FC1W  262144
#define OFF_FC2W  524288
__device__ hf g_w[786432];

__device__ hf g_rw[MTOK * C_DIM];
__device__ hf g_aw[MTOK * C_DIM];
__device__ hf g_q [MTOK * C_DIM];
__device__ hf g_kv[MTOK * 2 * C_DIM];
__device__ hf g_ao[MTOK * C_DIM];
__device__ hf g_h1[MTOK * C_DIM];
__device__ hf g_hb[MTOK * 1024];
__device__ float g_x[MTOK * C_DIM];

__device__ __forceinline__ int map_row(int i) {
    int b_ = i >> 6, n = i & 63;
    int bb = b_ >> 8, wi = b_ & 255;
    int sh = ((wi >> 4) << 3) + (n >> 3);
    int sw = ((wi & 15) << 3) + (n & 7);
    int gh = (sh + 4) & 127;
    int gw = (sw + 4) & 127;
    return (bb << 14) + (gh << 7) + gw;
}

__device__ __forceinline__ uint32_t smem_u32(const void* p) {
    return (uint32_t)__cvta_generic_to_shared(p);
}
__device__ __forceinline__ void ldsm4(uint32_t* r, uint32_t addr) {
    asm volatile("ldmatrix.sync.aligned.m8n8.x4.shared.b16 {%0,%1,%2,%3}, [%4];"
                 : "=r"(r[0]), "=r"(r[1]), "=r"(r[2]), "=r"(r[3]) : "r"(addr));
}
__device__ __forceinline__ void ldsm4t(uint32_t* r, uint32_t addr) {
    asm volatile("ldmatrix.sync.aligned.m8n8.x4.trans.shared.b16 {%0,%1,%2,%3}, [%4];"
                 : "=r"(r[0]), "=r"(r[1]), "=r"(r[2]), "=r"(r[3]) : "r"(addr));
}
__device__ __forceinline__ void mma_f16(float* c, const uint32_t* a, const uint32_t* b) {
    asm volatile("mma.sync.aligned.m16n8k16.row.col.f32.f16.f16.f32 "
                 "{%0,%1,%2,%3}, {%4,%5,%6,%7}, {%8,%9}, {%0,%1,%2,%3};"
                 : "+f"(c[0]), "+f"(c[1]), "+f"(c[2]), "+f"(c[3])
                 : "r"(a[0]), "r"(a[1]), "r"(a[2]), "r"(a[3]), "r"(b[0]), "r"(b[1]));
}
__device__ __forceinline__ void cp16(void* dst, const void* src) {
    asm volatile("cp.async.cg.shared.global [%0], [%1], 16;"
                 :: "r"(smem_u32(dst)), "l"(src));
}
__device__ __forceinline__ void cp_commit() { asm volatile("cp.async.commit_group;"); }

// ---------------------------------------------------------------------------
// merged weight convert: all 5 weights -> fp16 in one launch
// ---------------------------------------------------------------------------
__global__ void cvt_all_kernel(const float* __restrict__ qw, const float* __restrict__ kvw,
                               const float* __restrict__ pw, const float* __restrict__ f1w,
                               const float* __restrict__ f2w, hf* __restrict__ d)
{
    for (int i = blockIdx.x * blockDim.x + threadIdx.x; i < 786432;
         i += gridDim.x * blockDim.x) {
        float v;
        if (i < OFF_KVW)            v = qw[i];
        else if (i < OFF_PROJW)     v = kvw[i - OFF_KVW];
        else if (i < OFF_FC1W)      v = pw[i - OFF_PROJW];
        else if (i < OFF_FC2W)      v = f1w[i - OFF_FC1W];
        else                        v = f2w[i - OFF_FC2W];
        d[i] = __float2half(v);
    }
}

// ---------------------------------------------------------------------------
// LayerNorm: one warp per token, 8 tokens per block, fp16 out.
// ---------------------------------------------------------------------------
template<bool GATHER, bool DUAL>
__global__ void __launch_bounds__(256)
ln_kernel(const float* __restrict__ x1, const float* __restrict__ x2,
          const float* __restrict__ gam, const float* __restrict__ bet,
          hf* __restrict__ o1, hf* __restrict__ o2)
{
    int lane = threadIdx.x & 31, wid = threadIdx.x >> 5;
    int i = (blockIdx.x << 3) + wid;
    size_t base = (size_t)(GATHER ? map_row(i) : i) * C_DIM + (lane << 3);

    float a[8], b[8];
    *(float4*)(a)     = *(const float4*)&x1[base];
    *(float4*)(a + 4) = *(const float4*)&x1[base + 4];
    if (DUAL) {
        *(float4*)(b)     = *(const float4*)&x2[base];
        *(float4*)(b + 4) = *(const float4*)&x2[base + 4];
    }
    float s0 = 0, s1 = 0, s2 = 0, s3 = 0;
    #pragma unroll
    for (int j = 0; j < 8; j++) {
        s0 += a[j]; s1 += a[j] * a[j];
        if (DUAL) { s2 += b[j]; s3 += b[j] * b[j]; }
    }
    #pragma unroll
    for (int off = 16; off; off >>= 1) {
        s0 += __shfl_xor_sync(0xffffffffu, s0, off);
        s1 += __shfl_xor_sync(0xffffffffu, s1, off);
        if (DUAL) {
            s2 += __shfl_xor_sync(0xffffffffu, s2, off);
            s3 += __shfl_xor_sync(0xffffffffu, s3, off);
        }
    }
    float m1 = s0 * (1.0f / 256.0f);
    float r1 = rsqrtf(s1 * (1.0f / 256.0f) - m1 * m1 + 1e-5f);

    float g[8], bt[8];
    *(float4*)(g)      = *(const float4*)&gam[lane << 3];
    *(float4*)(g + 4)  = *(const float4*)&gam[(lane << 3) + 4];
    *(float4*)(bt)     = *(const float4*)&bet[lane << 3];
    *(float4*)(bt + 4) = *(const float4*)&bet[(lane << 3) + 4];

    size_t dst = (size_t)i * C_DIM + (lane << 3);
    hf t[8];
    #pragma unroll
    for (int j = 0; j < 8; j++) t[j] = __float2half((a[j] - m1) * r1 * g[j] + bt[j]);
    *(float4*)&o1[dst] = *(float4*)t;
    if (DUAL) {
        float m2 = s2 * (1.0f / 256.0f);
        float r2 = rsqrtf(s3 * (1.0f / 256.0f) - m2 * m2 + 1e-5f);
        #pragma unroll
        for (int j = 0; j < 8; j++) t[j] = __float2half((b[j] - m2) * r2 * g[j] + bt[j]);
        *(float4*)&o2[dst] = *(float4*)t;
    }
}

// ---------------------------------------------------------------------------
// fp16 tensor-core GEMM: C[M,N] = A[M,K] @ B[K,N] + bias.
// Block 128x128, warp 32x64 (8 warps, 4Mx2N), K-chunk 64, 2-stage cp.async.
// Dynamic SMEM 70KB, 2 CTAs/SM (reg-limited).
// MODE 0: bias -> fp16 | 1: bias+GELU -> fp16
// MODE 2: bias+scatter(map_row)+aux -> fp32 | 3: bias+aux -> fp32
// ---------------------------------------------------------------------------
#define AS_N (128 * 72)
#define BS_N (64 * 136)
#define AS_IDX(st,r,c) (((st) * 128 + (r)) * 72 + (c))
#define BS_IDX(st,r,c) (((st) * 64 + (r)) * 136 + (c))
#define SMEM_GEMM ((2 * AS_N + 2 * BS_N) * 2)    // 71680 B

template<int MODE>
__global__ void __launch_bounds__(256)
mma_gemm(const hf* __restrict__ Ah, const hf* __restrict__ Bh,
         const float* __restrict__ bias, const float* __restrict__ aux,
         hf* __restrict__ Chf, float* __restrict__ Cf,
         int M, int N, int K)
{
    extern __shared__ __align__(16) hf smg[];
    hf* As = smg;                   // [2][128][72]
    hf* Bs = smg + 2 * AS_N;        // [2][64][136]

    int tid = threadIdx.x;
    int lane = tid & 31, wid = tid >> 5;
    int wm = wid & 3, wn = wid >> 2;
    int rowBase = blockIdx.y << 7, colBase = blockIdx.x << 7;

    float acc[2][8][4];
    #pragma unroll
    for (int i = 0; i < 2; i++)
        #pragma unroll
        for (int j = 0; j < 8; j++)
            #pragma unroll
            for (int p = 0; p < 4; p++) acc[i][j][p] = 0.0f;

    int nc = K >> 6;

    auto stage_load = [&](int st, int k0) {
        // A: 128x64 hf = 1024 16B chunks, 4/thread
        #pragma unroll
        for (int l = 0; l < 4; l++) {
            int id = tid + (l << 8);
            int r = id >> 3, c8 = (id & 7) << 3;
            cp16(&As[AS_IDX(st, r, c8)], Ah + (size_t)(rowBase + r) * K + k0 + c8);
        }
        // B: 64x128 hf = 1024 16B chunks, 4/thread
        #pragma unroll
        for (int l = 0; l < 4; l++) {
            int id = tid + (l << 8);
            int r = id >> 4, c8 = (id & 15) << 3;
            cp16(&Bs[BS_IDX(st, r, c8)], Bh + (size_t)(k0 + r) * N + colBase + c8);
        }
    };

    stage_load(0, 0);
    cp_commit();

    for (int kt = 0; kt < nc; kt++) {
        if (kt + 1 < nc) {
            stage_load((kt + 1) & 1, (kt + 1) << 6);
            cp_commit();
            asm volatile("cp.async.wait_group 1;");
        } else {
            asm volatile("cp.async.wait_group 0;");
        }
        __syncthreads();

        int s = kt & 1;
        #pragma unroll
        for (int kk = 0; kk < 64; kk += 16) {
            uint32_t af[2][4];
            #pragma unroll
            for (int im = 0; im < 2; im++)
                ldsm4(af[im], smem_u32(&As[AS_IDX(s, wm * 32 + im * 16 + (lane & 15),
                                                  kk + ((lane >> 4) << 3))]));
            uint32_t bfr[4][4];
            #pragma unroll
            for (int jg = 0; jg < 4; jg++)
                ldsm4t(bfr[jg], smem_u32(&Bs[BS_IDX(s, kk + (lane & 15),
                                                    wn * 64 + jg * 16 + ((lane >> 4) << 3))]));
            #pragma unroll
            for (int im = 0; im < 2; im++)
                #pragma unroll
                for (int jn = 0; jn < 8; jn++)
                    mma_f16(acc[im][jn], af[im], &bfr[jn >> 1][(jn & 1) << 1]);
        }
        __syncthreads();
    }

    // epilogue
    int g = lane >> 2, t2 = (lane & 3) << 1;
    #pragma unroll
    for (int im = 0; im < 2; im++) {
        #pragma unroll
        for (int half_ = 0; half_ < 2; half_++) {
            int row = rowBase + wm * 32 + im * 16 + g + half_ * 8;
            size_t drow = (MODE == 2) ? (size_t)map_row(row) : (size_t)row;
            #pragma unroll
            for (int jn = 0; jn < 8; jn++) {
                int col = colBase + wn * 64 + jn * 8 + t2;
                float v0 = acc[im][jn][half_ * 2 + 0] + bias[col];
                float v1 = acc[im][jn][half_ * 2 + 1] + bias[col + 1];
                if (MODE == 1) {
                    v0 = 0.5f * v0 * (1.0f + erff(v0 * 0.70710678118654752f));
                    v1 = 0.5f * v1 * (1.0f + erff(v1 * 0.70710678118654752f));
                }
                if (MODE <= 1) {
                    __half2 t;
                    t.x = __float2half(v0);
                    t.y = __float2half(v1);
                    *(__half2*)(Chf + drow * (size_t)N + col) = t;
                } else {
                    const float* ax = aux + drow * (size_t)N + col;
                    *(float2*)(Cf + drow * (size_t)N + col) =
                        make_float2(v0 + ax[0], v1 + ax[1]);
                }
            }
        }
    }
}

// ---------------------------------------------------------------------------
// fp16 mma.sync attention: one block per (window, head), 256 threads.
// ---------------------------------------------------------------------------
__global__ void __launch_bounds__(256)
attn_kernel(const hf* __restrict__ Q, const hf* __restrict__ KV,
            const float* __restrict__ mask, const float* __restrict__ rel,
            hf* __restrict__ O)
{
    __shared__ __align__(16) hf qs[64 * 40];
    __shared__ __align__(16) hf ks[64 * 40];
    __shared__ __align__(16) hf vs[64 * 40];
    __shared__ __align__(16) float sc[64 * 68];
    __shared__ __align__(16) hf ps[64 * 72];

    int b_ = blockIdx.x, h = blockIdx.y, wi = b_ & 255;
    int tid = threadIdx.x, lane = tid & 31, wid = tid >> 5;
    int wm = wid & 3, wn = wid >> 2;

    #pragma unroll
    for (int l = 0; l < 3; l++) {
        int id = tid + (l << 8);
        int tsr = id >> 8;
        int rem = id & 255;
        int r = rem >> 2, c8 = (rem & 3) << 3;
        const hf* gsrc;
        hf* dst;
        if (tsr == 0) { gsrc = Q  + (size_t)(b_ * 64 + r) * 256 + h * 32 + c8;       dst = qs + r * 40 + c8; }
        else if (tsr == 1) { gsrc = KV + (size_t)(b_ * 64 + r) * 512 + h * 32 + c8;  dst = ks + r * 40 + c8; }
        else { gsrc = KV + (size_t)(b_ * 64 + r) * 512 + 256 + h * 32 + c8;          dst = vs + r * 40 + c8; }
        *(float4*)dst = *(const float4*)gsrc;
    }
    __syncthreads();

    float accS[4][4];
    #pragma unroll
    for (int j = 0; j < 4; j++)
        #pragma unroll
        for (int p = 0; p < 4; p++) accS[j][p] = 0.0f;

    #pragma unroll
    for (int kk = 0; kk < 32; kk += 16) {
        uint32_t ah[4];
        ldsm4(ah, smem_u32(qs + (wm * 16 + (lane & 15)) * 40 + kk + ((lane >> 4) << 3)));
        #pragma unroll
        for (int jg = 0; jg < 2; jg++) {
            int nrow = wn * 32 + jg * 16 + ((lane >> 4) << 3) + (lane & 7);
            int kcol = kk + (((lane >> 3) & 1) << 3);
            uint32_t bh[4];
            ldsm4(bh, smem_u32(ks + nrow * 40 + kcol));
            #pragma unroll
            for (int t = 0; t < 2; t++)
                mma_f16(accS[jg * 2 + t], ah, bh + t * 2);
        }
    }

    const float scale = 0.17677669529663687f;
    int g = lane >> 2, t2 = (lane & 3) << 1;
    #pragma unroll
    for (int jn = 0; jn < 4; jn++) {
        int col = wn * 32 + jn * 8 + t2;
        #pragma unroll
        for (int half_ = 0; half_ < 2; half_++) {
            int n = wm * 16 + g + half_ * 8;
            #pragma unroll
            for (int u = 0; u < 2; u++) {
                int m = col + u;
                int dr = (n >> 3) - (m >> 3) + 7;
                int dc = (n & 7) - (m & 7) + 7;
                sc[n * 68 + m] = accS[jn][half_ * 2 + u] * scale
                                 + rel[(dr * 15 + dc) * 8 + h]
                                 + mask[(size_t)wi * 4096 + n * 64 + m];
            }
        }
    }
    __syncthreads();

    {
        int row = tid >> 2, p = tid & 3;
        float e[16];
        float mx = -1e30f;
        #pragma unroll
        for (int j = 0; j < 16; j++) {
            e[j] = sc[row * 68 + p * 16 + j];
            mx = fmaxf(mx, e[j]);
        }
        mx = fmaxf(mx, __shfl_xor_sync(0xffffffffu, mx, 1));
        mx = fmaxf(mx, __shfl_xor_sync(0xffffffffu, mx, 2));
        float s = 0.0f;
        #pragma unroll
        for (int j = 0; j < 16; j++) { e[j] = __expf(e[j] - mx); s += e[j]; }
        s += __shfl_xor_sync(0xffffffffu, s, 1);
        s += __shfl_xor_sync(0xffffffffu, s, 2);
        float inv = 1.0f / s;
        hf t[16];
        #pragma unroll
        for (int j = 0; j < 16; j++) t[j] = __float2half(e[j] * inv);
        #pragma unroll
        for (int j = 0; j < 16; j += 8)
            *(float4*)&ps[row * 72 + p * 16 + j] = *(float4*)&t[j];
    }
    __syncthreads();

    float accO[2][4];
    #pragma unroll
    for (int t = 0; t < 2; t++)
        #pragma unroll
        for (int p = 0; p < 4; p++) accO[t][p] = 0.0f;

    #pragma unroll
    for (int kk = 0; kk < 64; kk += 16) {
        uint32_t ah[4];
        ldsm4(ah, smem_u32(ps + (wm * 16 + (lane & 15)) * 72 + kk + ((lane >> 4) << 3)));
        uint32_t bh[4];
        ldsm4t(bh, smem_u32(vs + (kk + (lane & 15)) * 40 + wn * 16 + ((lane >> 4) << 3)));
        #pragma unroll
        for (int t = 0; t < 2; t++)
            mma_f16(accO[t], ah, bh + t * 2);
    }

    #pragma unroll
    for (int t = 0; t < 2; t++) {
        int col = h * 32 + wn * 16 + t * 8 + t2;
        #pragma unroll
        for (int half_ = 0; half_ < 2; half_++) {
            size_t row = (size_t)b_ * 64 + wm * 16 + g + half_ * 8;
            __half2 o;
            o.x = __float2half(accO[t][half_ * 2 + 0]);
            o.y = __float2half(accO[t][half_ * 2 + 1]);
            *(__half2*)(O + row * 256 + col) = o;
        }
    }
}

// ---------------------------------------------------------------------------
extern "C" void kernel_launch(void* const* d_in, const int* in_sizes, int n_in,
                              void* d_out, int out_size)
{
    const float* ref    = (const float*)d_in[0];
    const float* adj    = (const float*)d_in[1];
    const float* mask   = (const float*)d_in[2];
    const float* n1g    = (const float*)d_in[5];
    const float* n1b    = (const float*)d_in[6];
    const float* q_w    = (const float*)d_in[7];
    const float* q_b    = (const float*)d_in[8];
    const float* kv_w   = (const float*)d_in[9];
    const float* kv_b   = (const float*)d_in[10];
    const float* rel    = (const float*)d_in[11];
    const float* proj_w = (const float*)d_in[12];
    const float* proj_b = (const float*)d_in[13];
    const float* n2g    = (const float*)d_in[14];
    const float* n2b    = (const float*)d_in[15];
    const float* fc1_w  = (const float*)d_in[16];
    const float* fc1_b  = (const float*)d_in[17];
    const float* fc2_w  = (const float*)d_in[18];
    const float* fc2_b  = (const float*)d_in[19];
    float* out = (float*)d_out;

    hf *w, *rw, *aw, *q, *kv, *ao, *h1, *hb;
    float* x;
    cudaGetSymbolAddress((void**)&w,  g_w);
    cudaGetSymbolAddress((void**)&rw, g_rw);
    cudaGetSymbolAddress((void**)&aw, g_aw);
    cudaGetSymbolAddress((void**)&q,  g_q);
    cudaGetSymbolAddress((void**)&kv, g_kv);
    cudaGetSymbolAddress((void**)&ao, g_ao);
    cudaGetSymbolAddress((void**)&h1, g_h1);
    cudaGetSymbolAddress((void**)&hb, g_hb);
    cudaGetSymbolAddress((void**)&x,  g_x);

    cudaFuncSetAttribute(mma_gemm<0>, cudaFuncAttributeMaxDynamicSharedMemorySize, SMEM_GEMM);
    cudaFuncSetAttribute(mma_gemm<1>, cudaFuncAttributeMaxDynamicSharedMemorySize, SMEM_GEMM);
    cudaFuncSetAttribute(mma_gemm<2>, cudaFuncAttributeMaxDynamicSharedMemorySize, SMEM_GEMM);
    cudaFuncSetAttribute(mma_gemm<3>, cudaFuncAttributeMaxDynamicSharedMemorySize, SMEM_GEMM);

    const int M = MTOK;
    const dim3 blk256(256);

    // 0. all weights -> fp16, one launch
    cvt_all_kernel<<<512, 256>>>(q_w, kv_w, proj_w, fc1_w, fc2_w, w);

    // 1. LN1 + shift + window partition
    ln_kernel<true, true><<<M / 8, blk256>>>(ref, adj, n1g, n1b, rw, aw);

    // 2. Q and KV projections
    mma_gemm<0><<<dim3(2, M / 128), blk256, SMEM_GEMM>>>(rw, w + OFF_QW,  q_b,  nullptr, q,  nullptr, M, 256, 256);
    mma_gemm<0><<<dim3(4, M / 128), blk256, SMEM_GEMM>>>(aw, w + OFF_KVW, kv_b, nullptr, kv, nullptr, M, 512, 256);

    // 3. windowed attention
    attn_kernel<<<dim3(2048, 8), blk256>>>(q, kv, mask, rel, ao);

    // 4. proj + window reverse + unshift + shortcut -> fp32 x
    mma_gemm<2><<<dim3(2, M / 128), blk256, SMEM_GEMM>>>(ao, w + OFF_PROJW, proj_b, ref, nullptr, x, M, 256, 256);

    // 5. MLP
    ln_kernel<false, false><<<M / 8, blk256>>>(x, nullptr, n2g, n2b, h1, nullptr);
    mma_gemm<1><<<dim3(8, M / 128), blk256, SMEM_GEMM>>>(h1, w + OFF_FC1W, fc1_b, nullptr, hb, nullptr, M, 1024, 256);
    mma_gemm<3><<<dim3(2, M / 128), blk256, SMEM_GEMM>>>(hb, w + OFF_FC2W, fc2_b, x, nullptr, out, M, 256, 1024);
}